// round 15
// baseline (speedup 1.0000x reference)
#include <cuda_runtime.h>
#include <math.h>
#include <stdint.h>

#define NTOK   20
#define DVEC   256
#define KSAMP  4096
#define NSTEP  19
#define SPB    4                 /* samples per block */
#define NBLK   (KSAMP/SPB)       /* 1024 blocks */
#define TPB    256               /* 8 warps */
#define GPW    (NSTEP*NTOK)      /* 380 keys per sample */

__device__ float          g_S[NTOK*6];   // [i][0..2]=x.Wf+b, [3..5]=x.Wa
__device__ float          g_score[KSAMP];
__device__ unsigned char  g_legal[KSAMP];
__device__ unsigned int   g_gmax_u = 0;       // int-mapped float max (reset)
__device__ int            g_cnt = 0;          // legal count (reset)
__device__ int            g_prep_done = 0;    // reset by last block
__device__ int            g_blocks_done = 0;  // reset by last block

// ---------------- Threefry-2x32 (20 rounds), identical to JAX ----------------
__host__ __device__ __forceinline__ void tf_block(uint32_t k0, uint32_t k1,
                                                  uint32_t x0, uint32_t x1,
                                                  uint32_t* o0, uint32_t* o1) {
  uint32_t ks2 = k0 ^ k1 ^ 0x1BD11BDAu;
  x0 += k0; x1 += k1;
#define TF_ROT(r) { x0 += x1; x1 = (x1 << (r)) | (x1 >> (32 - (r))); x1 ^= x0; }
  TF_ROT(13) TF_ROT(15) TF_ROT(26) TF_ROT(6)
  x0 += k1;  x1 += ks2 + 1u;
  TF_ROT(17) TF_ROT(29) TF_ROT(16) TF_ROT(24)
  x0 += ks2; x1 += k0 + 2u;
  TF_ROT(13) TF_ROT(15) TF_ROT(26) TF_ROT(6)
  x0 += k0;  x1 += k1 + 3u;
  TF_ROT(17) TF_ROT(29) TF_ROT(16) TF_ROT(24)
  x0 += k1;  x1 += ks2 + 4u;
  TF_ROT(13) TF_ROT(15) TF_ROT(26) TF_ROT(6)
  x0 += ks2; x1 += k0 + 5u;
#undef TF_ROT
  *o0 = x0; *o1 = x1;
}

__device__ __forceinline__ uint32_t tf_bits32(uint32_t k0, uint32_t k1, uint32_t i) {
  uint32_t a, b;
  tf_block(k0, k1, 0u, i, &a, &b);
  return a ^ b;
}

// ---------------- warp-per-token prep (lane owns 8 dims, shuffle-only) --------
__device__ __forceinline__ void prep_token(int i, int lane,
                                           const int* __restrict__ ids,
                                           const float* __restrict__ emb,
                                           const float* __restrict__ lv,
                                           const float* __restrict__ fx,
                                           const float* __restrict__ Wf,
                                           const float* __restrict__ Wa,
                                           const float* __restrict__ bop) {
  const unsigned FULL = 0xFFFFFFFFu;
  int id = ids[i];
  const float4* er = (const float4*)(emb + (size_t)id * DVEC);
  const float4* fr = (const float4*)(fx  + (size_t)id * DVEC);
  float4 e0 = er[lane * 2], e1 = er[lane * 2 + 1];
  float4 f0 = fr[lane * 2], f1 = fr[lane * 2 + 1];
  float lvv = lv[id];

  float ev[8] = {e0.x, e0.y, e0.z, e0.w, e1.x, e1.y, e1.z, e1.w};
  float fv[8] = {f0.x, f0.y, f0.z, f0.w, f1.x, f1.y, f1.z, f1.w};

  float m = ev[0];
#pragma unroll
  for (int j = 1; j < 8; j++) m = fmaxf(m, ev[j]);
#pragma unroll
  for (int o = 16; o; o >>= 1) m = fmaxf(m, __shfl_xor_sync(FULL, m, o));

  float ex[8]; float sm = 0.0f;
#pragma unroll
  for (int j = 0; j < 8; j++) { ex[j] = expf(ev[j] - m); sm += ex[j]; }
#pragma unroll
  for (int o = 16; o; o >>= 1) sm += __shfl_xor_sync(FULL, sm, o);

  float x[8];
#pragma unroll
  for (int j = 0; j < 8; j++) x[j] = (ex[j] / sm) * lvv + fv[j];

  float p[6] = {0, 0, 0, 0, 0, 0};
#pragma unroll
  for (int j = 0; j < 8; j++) {
    int d = lane * 8 + j;
    p[0] += x[j] * Wf[d * 3 + 0];
    p[1] += x[j] * Wf[d * 3 + 1];
    p[2] += x[j] * Wf[d * 3 + 2];
    p[3] += x[j] * Wa[d * 3 + 0];
    p[4] += x[j] * Wa[d * 3 + 1];
    p[5] += x[j] * Wa[d * 3 + 2];
  }
#pragma unroll
  for (int o = 16; o; o >>= 1) {
#pragma unroll
    for (int q = 0; q < 6; q++) p[q] += __shfl_xor_sync(FULL, p[q], o);
  }
  if (lane == 0) {
#pragma unroll
    for (int q = 0; q < 6; q++)
      g_S[i * 6 + q] = p[q] + (q < 3 ? bop[q] : 0.0f);
    __threadfence();
    atomicAdd(&g_prep_done, 1);
  }
}

// ---------------- single fused kernel: interleaved keygen + warp scan ---------
__global__ __launch_bounds__(TPB) void fused_all(
    uint32_t kop0, uint32_t kop1, uint32_t kg0, uint32_t kg1,
    const int* __restrict__ ids, const float* __restrict__ emb,
    const float* __restrict__ lv, const float* __restrict__ fx,
    const float* __restrict__ Wf, const float* __restrict__ Wa,
    const float* __restrict__ bop, float* __restrict__ out) {
  __shared__ uint32_t skey[SPB][384];   // 380 used + 4 pad per sample
  __shared__ float    sS[NTOK * 6];
  __shared__ float    sred[TPB];
  __shared__ int      scnt[SPB];

  const unsigned FULL = 0xFFFFFFFFu;
  int tid = threadIdx.x;
  int lane = tid & 31, w = tid >> 5;
  int k0b = blockIdx.x * SPB;

  // blocks 0..19, warp 0: prep one token (overlaps everyone's keygen)
  if (blockIdx.x < NTOK && w == 0)
    prep_token(blockIdx.x, lane, ids, emb, lv, fx, Wf, Wa, bop);

  // ---- keygen: 6 hashes per thread, EXPLICITLY interleaved (ILP=6) ----
  // flat slot f = tid + 256*r covers [0,1536) = SPB*384 (pad slots harmless)
  {
    uint32_t a0[6], a1[6], jj[6];
#pragma unroll
    for (int r = 0; r < 6; r++) {
      int f = tid + TPB * r;
      int si = f / 384, l = f - si * 384;
      int t = l / 20, j = l - t * 20;
      jj[r] = (uint32_t)j;
      uint32_t ctr = (uint32_t)t * 81920u + (uint32_t)(k0b + si) * 20u + (uint32_t)j;
      a0[r] = kg0;                 // x0 = 0 + k0
      a1[r] = ctr + kg1;           // x1 = ctr + k1
    }
    uint32_t ks2 = kg0 ^ kg1 ^ 0x1BD11BDAu;
#define R6(rot) _Pragma("unroll") for (int r = 0; r < 6; r++) { \
      a0[r] += a1[r]; a1[r] = (a1[r] << (rot)) | (a1[r] >> (32 - (rot))); a1[r] ^= a0[r]; }
#define INJ6(ka, kb, c) _Pragma("unroll") for (int r = 0; r < 6; r++) { \
      a0[r] += (ka); a1[r] += (kb) + (c); }
    R6(13) R6(15) R6(26) R6(6)   INJ6(kg1, ks2, 1u)
    R6(17) R6(29) R6(16) R6(24)  INJ6(ks2, kg0, 2u)
    R6(13) R6(15) R6(26) R6(6)   INJ6(kg0, kg1, 3u)
    R6(17) R6(29) R6(16) R6(24)  INJ6(kg1, ks2, 4u)
    R6(13) R6(15) R6(26) R6(6)   INJ6(ks2, kg0, 5u)
#undef R6
#undef INJ6
#pragma unroll
    for (int r = 0; r < 6; r++) {
      int f = tid + TPB * r;
      int si = f / 384, l = f - si * 384;
      uint32_t key = (a0[r] ^ a1[r]) >> 9;   // gumbel order == bits>>9
      skey[si][l] = ((key + 1u) << 5) | (31u - jj[r]);
    }
  }

  // block-level wait for the 20 prep warps, then stage sS
  if (tid == 0) {
    while (*((volatile int*)&g_prep_done) != NTOK) __nanosleep(40);
  }
  __syncthreads();
  __threadfence();                       // acquire g_S
  if (tid < NTOK * 6) sS[tid] = g_S[tid];
  __syncthreads();

  // ---- warps 0..3 scan one sample each ----
  if (w < SPB) {
    int k = k0b + w;

    // ops: lane t computes step t's op; pack into two ballot words
    uint32_t opbits = tf_bits32(kop0, kop1, (uint32_t)(lane * KSAMP + k));
    int my_op = (int)(((opbits >> 16) % 3u + (opbits & 0xFFFFu) % 3u) % 3u);
    uint32_t opb0 = __ballot_sync(FULL, my_op & 1);
    uint32_t opb1 = __ballot_sync(FULL, my_op & 2);

    unsigned avail = 0xFFFFFu, f1 = 0u, f2 = 0u;
    unsigned long long plo = 0ull, phi = 0ull;   // ptr[20], 5 bits/slot
#pragma unroll
    for (int j = 0; j < 12; j++) plo |= (unsigned long long)j << (5 * j);
#pragma unroll
    for (int j = 12; j < 20; j++) phi |= (unsigned long long)j << (5 * (j - 12));

    float score = 0.0f;
    bool legal = true;

#pragma unroll
    for (int t = 0; t < NSTEP; t++) {
      int op = (int)(((opb0 >> t) & 1u) | (((opb1 >> t) & 1u) << 1));

      uint32_t s = (lane < NTOK && ((avail >> lane) & 1u)) ? skey[w][t * 20 + lane] : 0u;

      uint32_t m1 = __reduce_max_sync(FULL, s);
      int b1 = (int)((~m1) & 31u);                     // low-index tie-break
      uint32_t s2 = (lane == b1) ? 0u : s;
      uint32_t m2 = __reduce_max_sync(FULL, s2);
      int b2 = (int)((~m2) & 31u);

      avail &= ~(1u << b2);

      // replicated packed-ptr extract (pure ALU; no shfl)
      int s1 = 5 * b1, s2s = 5 * b2;
      int s1l = (s1 < 60) ? s1 : 0,  s1h = (s1 >= 60) ? s1 - 60 : 0;
      int s2l = (s2s < 60) ? s2s : 0, s2h = (s2s >= 60) ? s2s - 60 : 0;
      int pf = (int)((b1 < 12 ? (plo >> s1l) : (phi >> s1h)) & 31ull);
      int pa = (int)((b2 < 12 ? (plo >> s2l) : (phi >> s2h)) & 31ull);
      score += sS[pf * 6 + op] + sS[pa * 6 + 3 + op];  // broadcast LDS, off-chain

      unsigned of1 = (f1 >> b1) & 1u;
      unsigned of2 = (f2 >> b1) & 1u;
      bool bad = ((op != 2) && of1) || ((op == 1) && of2);
      legal = legal && !bad;

      if (op == 2) {                     // mod: slot b1 := copy of slot b2
        if (b1 < 12) plo = (plo & ~(31ull << s1l)) | ((unsigned long long)pa << s1l);
        else         phi = (phi & ~(31ull << s1h)) | ((unsigned long long)pa << s1h);
        unsigned a1 = (f1 >> b2) & 1u, a2 = (f2 >> b2) & 1u;
        f1 = (f1 & ~(1u << b1)) | (a1 << b1);
        f2 = (f2 & ~(1u << b1)) | (a2 << b1);
      } else if (op == 0) {
        f1 |= 1u << b1;
      } else {
        f2 |= 1u << b1;
      }
    }

    if (lane == 0) {
      g_score[k] = score;
      g_legal[k] = legal ? 1 : 0;
      sred[w] = legal ? score : -INFINITY;
      scnt[w] = legal ? 1 : 0;
    }
  }
  __syncthreads();

  if (tid == 0) {
    float bm = sred[0]; int bc = scnt[0];
#pragma unroll
    for (int q = 1; q < SPB; q++) { bm = fmaxf(bm, sred[q]); bc += scnt[q]; }
    if (bc > 0) {
      int sv = __float_as_int(bm);
      unsigned enc = (unsigned)sv ^ (((unsigned)(sv >> 31)) | 0x80000000u);
      atomicMax(&g_gmax_u, enc);
    }
    atomicAdd(&g_cnt, bc);
    __threadfence();
    int last = (atomicAdd(&g_blocks_done, 1) == NBLK - 1);
    sred[0] = (float)last;
  }
  __syncthreads();
  if (sred[0] == 0.0f) return;
  __threadfence();                       // acquire scores/legal/max/cnt

  unsigned genc = g_gmax_u;
  int cnt = g_cnt;
  int gs = (genc & 0x80000000u) ? (int)(genc ^ 0x80000000u) : (int)(~genc);
  float gm = __int_as_float(gs);

  float sum = 0.0f;
  int q0 = tid * (KSAMP / TPB);          // 16 samples per thread
#pragma unroll
  for (int q = 0; q < KSAMP / TPB; q += 4) {
    float4 sc = *(const float4*)(g_score + q0 + q);
    uchar4 lg = *(const uchar4*)(g_legal + q0 + q);
    if (lg.x) sum += __expf(sc.x - gm);
    if (lg.y) sum += __expf(sc.y - gm);
    if (lg.z) sum += __expf(sc.z - gm);
    if (lg.w) sum += __expf(sc.w - gm);
  }
  __syncthreads();
  sred[tid] = sum; __syncthreads();
  for (int st = TPB / 2; st > 0; st >>= 1) {
    if (tid < st) sred[tid] += sred[tid + st];
    __syncthreads();
  }

  if (tid == 0) {
    float lse = gm + logf(sred[0]);
    double log_all = lgamma(21.0) + log(1767263190.0) + 19.0 * log(3.0);
    double res = log_all + (double)logf((float)cnt) - 2.0 * log(4096.0) + (double)lse;
    out[0] = (float)res;
    g_blocks_done = 0;                   // reset for next graph replay
    g_cnt = 0;
    g_gmax_u = 0u;
    g_prep_done = 0;
  }
}

// ---------------- Launch ------------------------------------------------------
extern "C" void kernel_launch(void* const* d_in, const int* in_sizes, int n_in,
                              void* d_out, int out_size) {
  const int*   ids = (const int*)d_in[0];
  const float* emb = (const float*)d_in[1];
  const float* lv  = (const float*)d_in[2];
  const float* fx  = (const float*)d_in[3];
  const float* Wf  = (const float*)d_in[4];
  const float* Wa  = (const float*)d_in[5];
  const float* bop = (const float*)d_in[6];
  float* out = (float*)d_out;

  // jax.random.key(42) -> (0,42); partitionable foldlike split
  uint32_t kop0, kop1, kg0, kg1;
  tf_block(0u, 42u, 0u, 0u, &kop0, &kop1);
  tf_block(0u, 42u, 0u, 1u, &kg0, &kg1);

  fused_all<<<NBLK, TPB>>>(kop0, kop1, kg0, kg1,
                           ids, emb, lv, fx, Wf, Wa, bop, out);
}

// round 16
// speedup vs baseline: 1.0014x; 1.0014x over previous
#include <cuda_runtime.h>
#include <math.h>
#include <stdint.h>

#define NTOK   20
#define DVEC   256
#define KSAMP  4096
#define NSTEP  19
#define SPB    4                 /* samples per block */
#define NBLK   (KSAMP/SPB)       /* 1024 blocks */
#define TPB    256               /* 8 warps */
#define GPW    (NSTEP*NTOK)      /* 380 keys per sample */

__device__ float          g_S[NTOK*6];   // [i][0..2]=x.Wf+b, [3..5]=x.Wa
__device__ float          g_score[KSAMP];
__device__ unsigned char  g_legal[KSAMP];
__device__ unsigned int   g_gmax_u = 0;       // int-mapped float max (reset)
__device__ int            g_cnt = 0;          // legal count (reset)
__device__ int            g_prep_done = 0;    // reset by last block
__device__ int            g_blocks_done = 0;  // reset by last block

// add via IMAD on the FMA pipe: x = y*one + x  (one is an opaque kernel arg =1)
#define MADD(x, y) asm("mad.lo.u32 %0, %1, %2, %0;" : "+r"(x) : "r"(y), "r"(one))

// ---------------- Threefry-2x32 (20 rounds), identical to JAX ----------------
__host__ __device__ __forceinline__ void tf_block(uint32_t k0, uint32_t k1,
                                                  uint32_t x0, uint32_t x1,
                                                  uint32_t* o0, uint32_t* o1) {
  uint32_t ks2 = k0 ^ k1 ^ 0x1BD11BDAu;
  x0 += k0; x1 += k1;
#define TF_ROT(r) { x0 += x1; x1 = (x1 << (r)) | (x1 >> (32 - (r))); x1 ^= x0; }
  TF_ROT(13) TF_ROT(15) TF_ROT(26) TF_ROT(6)
  x0 += k1;  x1 += ks2 + 1u;
  TF_ROT(17) TF_ROT(29) TF_ROT(16) TF_ROT(24)
  x0 += ks2; x1 += k0 + 2u;
  TF_ROT(13) TF_ROT(15) TF_ROT(26) TF_ROT(6)
  x0 += k0;  x1 += k1 + 3u;
  TF_ROT(17) TF_ROT(29) TF_ROT(16) TF_ROT(24)
  x0 += k1;  x1 += ks2 + 4u;
  TF_ROT(13) TF_ROT(15) TF_ROT(26) TF_ROT(6)
  x0 += ks2; x1 += k0 + 5u;
#undef TF_ROT
  *o0 = x0; *o1 = x1;
}

__device__ __forceinline__ uint32_t tf_bits32(uint32_t k0, uint32_t k1, uint32_t i) {
  uint32_t a, b;
  tf_block(k0, k1, 0u, i, &a, &b);
  return a ^ b;
}

// ---------------- warp-per-token prep (lane owns 8 dims, shuffle-only) --------
__device__ __forceinline__ void prep_token(int i, int lane,
                                           const int* __restrict__ ids,
                                           const float* __restrict__ emb,
                                           const float* __restrict__ lv,
                                           const float* __restrict__ fx,
                                           const float* __restrict__ Wf,
                                           const float* __restrict__ Wa,
                                           const float* __restrict__ bop) {
  const unsigned FULL = 0xFFFFFFFFu;
  int id = ids[i];
  const float4* er = (const float4*)(emb + (size_t)id * DVEC);
  const float4* fr = (const float4*)(fx  + (size_t)id * DVEC);
  float4 e0 = er[lane * 2], e1 = er[lane * 2 + 1];
  float4 f0 = fr[lane * 2], f1 = fr[lane * 2 + 1];
  float lvv = lv[id];

  float ev[8] = {e0.x, e0.y, e0.z, e0.w, e1.x, e1.y, e1.z, e1.w};
  float fv[8] = {f0.x, f0.y, f0.z, f0.w, f1.x, f1.y, f1.z, f1.w};

  float m = ev[0];
#pragma unroll
  for (int j = 1; j < 8; j++) m = fmaxf(m, ev[j]);
#pragma unroll
  for (int o = 16; o; o >>= 1) m = fmaxf(m, __shfl_xor_sync(FULL, m, o));

  float ex[8]; float sm = 0.0f;
#pragma unroll
  for (int j = 0; j < 8; j++) { ex[j] = expf(ev[j] - m); sm += ex[j]; }
#pragma unroll
  for (int o = 16; o; o >>= 1) sm += __shfl_xor_sync(FULL, sm, o);

  float x[8];
#pragma unroll
  for (int j = 0; j < 8; j++) x[j] = (ex[j] / sm) * lvv + fv[j];

  float p[6] = {0, 0, 0, 0, 0, 0};
#pragma unroll
  for (int j = 0; j < 8; j++) {
    int d = lane * 8 + j;
    p[0] += x[j] * Wf[d * 3 + 0];
    p[1] += x[j] * Wf[d * 3 + 1];
    p[2] += x[j] * Wf[d * 3 + 2];
    p[3] += x[j] * Wa[d * 3 + 0];
    p[4] += x[j] * Wa[d * 3 + 1];
    p[5] += x[j] * Wa[d * 3 + 2];
  }
#pragma unroll
  for (int o = 16; o; o >>= 1) {
#pragma unroll
    for (int q = 0; q < 6; q++) p[q] += __shfl_xor_sync(FULL, p[q], o);
  }
  if (lane == 0) {
#pragma unroll
    for (int q = 0; q < 6; q++)
      g_S[i * 6 + q] = p[q] + (q < 3 ? bop[q] : 0.0f);
    __threadfence();
    atomicAdd(&g_prep_done, 1);
  }
}

// ---------------- single fused kernel: pipe-balanced keygen + warp scan -------
__global__ __launch_bounds__(TPB) void fused_all(
    uint32_t kop0, uint32_t kop1, uint32_t kg0, uint32_t kg1, uint32_t one,
    const int* __restrict__ ids, const float* __restrict__ emb,
    const float* __restrict__ lv, const float* __restrict__ fx,
    const float* __restrict__ Wf, const float* __restrict__ Wa,
    const float* __restrict__ bop, float* __restrict__ out) {
  __shared__ uint32_t skey[SPB][384];   // 380 used + 4 pad per sample
  __shared__ float    sS[NTOK * 6];
  __shared__ float    sred[TPB];
  __shared__ int      scnt[SPB];

  const unsigned FULL = 0xFFFFFFFFu;
  int tid = threadIdx.x;
  int lane = tid & 31, w = tid >> 5;
  int k0b = blockIdx.x * SPB;

  // blocks 0..19, warp 0: prep one token (overlaps everyone's keygen)
  if (blockIdx.x < NTOK && w == 0)
    prep_token(blockIdx.x, lane, ids, emb, lv, fx, Wf, Wa, bop);

  // scan warps: ops hash + ballots EARLY (off the post-barrier tail)
  uint32_t opb0 = 0, opb1 = 0;
  if (w < SPB) {
    int k = k0b + w;
    uint32_t opbits = tf_bits32(kop0, kop1, (uint32_t)(lane * KSAMP + k));
    int my_op = (int)(((opbits >> 16) % 3u + (opbits & 0xFFFFu) % 3u) % 3u);
    opb0 = __ballot_sync(FULL, my_op & 1);
    opb1 = __ballot_sync(FULL, my_op & 2);
  }

  // ---- keygen: 6 hashes per thread, interleaved, adds on the FMA pipe ----
  {
    uint32_t a0[6], a1[6], jj[6];
#pragma unroll
    for (int r = 0; r < 6; r++) {
      int f = tid + TPB * r;
      int si = f / 384, l = f - si * 384;
      int t = l / 20, j = l - t * 20;
      jj[r] = (uint32_t)j;
      uint32_t ctr = (uint32_t)t * 81920u + (uint32_t)(k0b + si) * 20u + (uint32_t)j;
      a0[r] = kg0;                 // x0 = 0 + k0
      a1[r] = ctr + kg1;           // x1 = ctr + k1
    }
    uint32_t ks2 = kg0 ^ kg1 ^ 0x1BD11BDAu;
#define R6(rot) _Pragma("unroll") for (int r = 0; r < 6; r++) { \
      MADD(a0[r], a1[r]); a1[r] = (a1[r] << (rot)) | (a1[r] >> (32 - (rot))); a1[r] ^= a0[r]; }
#define INJ6(ka, kb, c) { uint32_t kb_c = (kb) + (c); \
      _Pragma("unroll") for (int r = 0; r < 6; r++) { \
      MADD(a0[r], (ka)); MADD(a1[r], kb_c); } }
    R6(13) R6(15) R6(26) R6(6)   INJ6(kg1, ks2, 1u)
    R6(17) R6(29) R6(16) R6(24)  INJ6(ks2, kg0, 2u)
    R6(13) R6(15) R6(26) R6(6)   INJ6(kg0, kg1, 3u)
    R6(17) R6(29) R6(16) R6(24)  INJ6(kg1, ks2, 4u)
    R6(13) R6(15) R6(26) R6(6)   INJ6(ks2, kg0, 5u)
#undef R6
#undef INJ6
#pragma unroll
    for (int r = 0; r < 6; r++) {
      int f = tid + TPB * r;
      int si = f / 384, l = f - si * 384;
      uint32_t key = (a0[r] ^ a1[r]) >> 9;   // gumbel order == bits>>9
      skey[si][l] = ((key + 1u) << 5) | (31u - jj[r]);
    }
  }

  // block-level wait for the 20 prep warps, then stage sS
  if (tid == 0) {
    while (*((volatile int*)&g_prep_done) != NTOK) __nanosleep(40);
  }
  __syncthreads();
  __threadfence();                       // acquire g_S
  if (tid < NTOK * 6) sS[tid] = g_S[tid];
  __syncthreads();

  // ---- warps 0..3 scan one sample each ----
  if (w < SPB) {
    int k = k0b + w;

    unsigned avail = 0xFFFFFu, f1 = 0u, f2 = 0u;
    unsigned long long plo = 0ull, phi = 0ull;   // ptr[20], 5 bits/slot
#pragma unroll
    for (int j = 0; j < 12; j++) plo |= (unsigned long long)j << (5 * j);
#pragma unroll
    for (int j = 12; j < 20; j++) phi |= (unsigned long long)j << (5 * (j - 12));

    float score = 0.0f;
    bool legal = true;

#pragma unroll
    for (int t = 0; t < NSTEP; t++) {
      int op = (int)(((opb0 >> t) & 1u) | (((opb1 >> t) & 1u) << 1));

      uint32_t s = (lane < NTOK && ((avail >> lane) & 1u)) ? skey[w][t * 20 + lane] : 0u;

      uint32_t m1 = __reduce_max_sync(FULL, s);
      int b1 = (int)((~m1) & 31u);                     // low-index tie-break
      uint32_t s2 = (lane == b1) ? 0u : s;
      uint32_t m2 = __reduce_max_sync(FULL, s2);
      int b2 = (int)((~m2) & 31u);

      avail &= ~(1u << b2);

      // replicated packed-ptr extract (pure ALU; no shfl)
      int s1 = 5 * b1, s2s = 5 * b2;
      int s1l = (s1 < 60) ? s1 : 0,  s1h = (s1 >= 60) ? s1 - 60 : 0;
      int s2l = (s2s < 60) ? s2s : 0, s2h = (s2s >= 60) ? s2s - 60 : 0;
      int pf = (int)((b1 < 12 ? (plo >> s1l) : (phi >> s1h)) & 31ull);
      int pa = (int)((b2 < 12 ? (plo >> s2l) : (phi >> s2h)) & 31ull);
      score += sS[pf * 6 + op] + sS[pa * 6 + 3 + op];  // broadcast LDS, off-chain

      unsigned of1 = (f1 >> b1) & 1u;
      unsigned of2 = (f2 >> b1) & 1u;
      bool bad = ((op != 2) && of1) || ((op == 1) && of2);
      legal = legal && !bad;

      if (op == 2) {                     // mod: slot b1 := copy of slot b2
        if (b1 < 12) plo = (plo & ~(31ull << s1l)) | ((unsigned long long)pa << s1l);
        else         phi = (phi & ~(31ull << s1h)) | ((unsigned long long)pa << s1h);
        unsigned a1 = (f1 >> b2) & 1u, a2 = (f2 >> b2) & 1u;
        f1 = (f1 & ~(1u << b1)) | (a1 << b1);
        f2 = (f2 & ~(1u << b1)) | (a2 << b1);
      } else if (op == 0) {
        f1 |= 1u << b1;
      } else {
        f2 |= 1u << b1;
      }
    }

    if (lane == 0) {
      g_score[k] = score;
      g_legal[k] = legal ? 1 : 0;
      sred[w] = legal ? score : -INFINITY;
      scnt[w] = legal ? 1 : 0;
    }
  }
  __syncthreads();

  if (tid == 0) {
    float bm = sred[0]; int bc = scnt[0];
#pragma unroll
    for (int q = 1; q < SPB; q++) { bm = fmaxf(bm, sred[q]); bc += scnt[q]; }
    if (bc > 0) {
      int sv = __float_as_int(bm);
      unsigned enc = (unsigned)sv ^ (((unsigned)(sv >> 31)) | 0x80000000u);
      atomicMax(&g_gmax_u, enc);
    }
    atomicAdd(&g_cnt, bc);
    __threadfence();
    int last = (atomicAdd(&g_blocks_done, 1) == NBLK - 1);
    sred[0] = (float)last;
  }
  __syncthreads();
  if (sred[0] == 0.0f) return;
  __threadfence();                       // acquire scores/legal/max/cnt

  unsigned genc = g_gmax_u;
  int cnt = g_cnt;
  int gs = (genc & 0x80000000u) ? (int)(genc ^ 0x80000000u) : (int)(~genc);
  float gm = __int_as_float(gs);

  float sum = 0.0f;
  int q0 = tid * (KSAMP / TPB);          // 16 samples per thread
#pragma unroll
  for (int q = 0; q < KSAMP / TPB; q += 4) {
    float4 sc = *(const float4*)(g_score + q0 + q);
    uchar4 lg = *(const uchar4*)(g_legal + q0 + q);
    if (lg.x) sum += __expf(sc.x - gm);
    if (lg.y) sum += __expf(sc.y - gm);
    if (lg.z) sum += __expf(sc.z - gm);
    if (lg.w) sum += __expf(sc.w - gm);
  }
  __syncthreads();
  sred[tid] = sum; __syncthreads();
  for (int st = TPB / 2; st > 0; st >>= 1) {
    if (tid < st) sred[tid] += sred[tid + st];
    __syncthreads();
  }

  if (tid == 0) {
    float lse = gm + logf(sred[0]);
    double log_all = lgamma(21.0) + log(1767263190.0) + 19.0 * log(3.0);
    double res = log_all + (double)logf((float)cnt) - 2.0 * log(4096.0) + (double)lse;
    out[0] = (float)res;
    g_blocks_done = 0;                   // reset for next graph replay
    g_cnt = 0;
    g_gmax_u = 0u;
    g_prep_done = 0;
  }
}

// ---------------- Launch ------------------------------------------------------
extern "C" void kernel_launch(void* const* d_in, const int* in_sizes, int n_in,
                              void* d_out, int out_size) {
  const int*   ids = (const int*)d_in[0];
  const float* emb = (const float*)d_in[1];
  const float* lv  = (const float*)d_in[2];
  const float* fx  = (const float*)d_in[3];
  const float* Wf  = (const float*)d_in[4];
  const float* Wa  = (const float*)d_in[5];
  const float* bop = (const float*)d_in[6];
  float* out = (float*)d_out;

  // jax.random.key(42) -> (0,42); partitionable foldlike split
  uint32_t kop0, kop1, kg0, kg1;
  tf_block(0u, 42u, 0u, 0u, &kop0, &kop1);
  tf_block(0u, 42u, 0u, 1u, &kg0, &kg1);

  fused_all<<<NBLK, TPB>>>(kop0, kop1, kg0, kg1, 1u,
                           ids, emb, lv, fx, Wf, Wa, bop, out);
}